// round 9
// baseline (speedup 1.0000x reference)
#include <cuda_runtime.h>
#include <cuda_bf16.h>
#include <cstdint>
#include <math.h>

#define BB 32
#define NN 540
#define DD 512
#define HH 8
#define DHE 64
#define HB (HH*BB)          // 256
#define BN (BB*NN)          // 17280
#define PCLIP 539
#define RLEN (2*PCLIP+1)    // 1079

// -------- scratch (device globals) --------
// q/k/v stored as packed bf16x2 (32 words per row of 64); q pre-scaled 0.125
__device__ uint32_t g_q[(size_t)HB*NN*32];
__device__ uint32_t g_k[(size_t)HB*NN*32];
__device__ uint32_t g_v[(size_t)HB*NN*32];
__device__ uint32_t g_posbf[(size_t)RLEN*32];   // pos_k as bf16x2
__device__ float g_ao[(size_t)HB*NN*DHE];       // attn@v, tf32 bits, head-major
__device__ float g_o[(size_t)BN*DD];            // pre-LN (fp32)

// -------- helpers --------
__device__ __forceinline__ uint32_t f2tf(float f) {
    uint32_t u;
    asm("cvt.rna.tf32.f32 %0, %1;" : "=r"(u) : "f"(f));
    return u;
}
__device__ __forceinline__ uint32_t f2bf2(float lo, float hi) {
    uint32_t r;
    asm("cvt.rn.bf16x2.f32 %0, %1, %2;" : "=r"(r) : "f"(hi), "f"(lo));
    return r;
}

__device__ __forceinline__ void mma_tf32(float c[4],
                                         uint32_t a0, uint32_t a1, uint32_t a2, uint32_t a3,
                                         uint32_t b0, uint32_t b1) {
    asm volatile(
        "mma.sync.aligned.m16n8k8.row.col.f32.tf32.tf32.f32 "
        "{%0,%1,%2,%3}, {%4,%5,%6,%7}, {%8,%9}, {%0,%1,%2,%3};\n"
        : "+f"(c[0]), "+f"(c[1]), "+f"(c[2]), "+f"(c[3])
        : "r"(a0), "r"(a1), "r"(a2), "r"(a3), "r"(b0), "r"(b1));
}

__device__ __forceinline__ void mma_bf16(float c[4],
                                         uint32_t a0, uint32_t a1, uint32_t a2, uint32_t a3,
                                         uint32_t b0, uint32_t b1) {
    asm volatile(
        "mma.sync.aligned.m16n8k16.row.col.f32.bf16.bf16.f32 "
        "{%0,%1,%2,%3}, {%4,%5,%6,%7}, {%8,%9}, {%0,%1,%2,%3};\n"
        : "+f"(c[0]), "+f"(c[1]), "+f"(c[2]), "+f"(c[3])
        : "r"(a0), "r"(a1), "r"(a2), "r"(a3), "r"(b0), "r"(b1));
}

__device__ __forceinline__ void cp16(uint32_t smem_u32_addr, const void* gptr) {
    asm volatile("cp.async.cg.shared.global [%0], [%1], 16;\n"
                 :: "r"(smem_u32_addr), "l"(gptr));
}
#define CP_COMMIT() asm volatile("cp.async.commit_group;\n" ::)
#define CP_WAIT(n)  asm volatile("cp.async.wait_group %0;\n" :: "n"(n))

// smem tiling constants for pipelined GEMMs (tf32 kernels)
#define XS_STRIDE 36
#define X_TILE_U32 (128*XS_STRIDE)     // 4608
#define BS_STRIDE 68
#define B_TILE_U32 (32*BS_STRIDE)      // 2176
#define OBS_STRIDE 132
#define OB_TILE_U32 (32*OBS_STRIDE)    // 4224

// flash smem layout (u32 offsets)
// bf16 rows of 64 elements = 32 data words + 4 pad = stride 36
#define STKV 36
#define STX 68
#define QS_OFF 0
#define KS_OFF (64*STKV)               // 2304
#define VS_OFF (2*64*STKV)             // 4608
#define PP_OFF (3*64*STKV)             // 6912
#define X0_OFF (4*64*STKV)             // 9216
#define X1_OFF (X0_OFF + 64*STX)       // 13568
#define FLASH_U32 (X1_OFF + 64*STX)    // 17920 -> 71680 B (3 blocks/SM)

// ============================================================
// K0: pos_k fp32 -> bf16x2
// ============================================================
__global__ void pos2bf_kernel(const float* __restrict__ pos_k)
{
    int i = blockIdx.x * 256 + threadIdx.x;
    if (i < RLEN * 32) {
        float2 v = ((const float2*)pos_k)[i];
        g_posbf[i] = f2bf2(v.x, v.y);
    }
}

// ============================================================
// K1: fused QKV projection, tf32 mma, cp.async 2-stage pipeline.
// Outputs packed bf16, head-major. q pre-scaled by 0.125.
// ============================================================
__global__ __launch_bounds__(256) void qkv_fused(const float* __restrict__ X,
                                                 const float* __restrict__ Wq, const float* __restrict__ bq,
                                                 const float* __restrict__ Wk, const float* __restrict__ bk,
                                                 const float* __restrict__ Wv, const float* __restrict__ bv)
{
    extern __shared__ uint32_t smbuf[];
    const uint32_t smem_base = (uint32_t)__cvta_generic_to_shared(smbuf);

    const int tid = threadIdx.x;
    const int lane = tid & 31, warp = tid >> 5;
    const int g = lane >> 2, t = lane & 3;
    const int wm = warp >> 1, wn = warp & 1;
    const int m0 = blockIdx.x * 128;
    const int n0 = blockIdx.y * 64;

    const float* Ws[3] = {Wq, Wk, Wv};

    const int xrow[4] = { (tid) >> 3, (tid + 256) >> 3, (tid + 512) >> 3, (tid + 768) >> 3 };
    const int xcol4 = (tid & 7) * 4;
    const int brow[2] = { tid >> 4, (tid + 256) >> 4 };
    const int bcol4 = (tid & 15) * 4;

    float acc[3][2][4][4];
    #pragma unroll
    for (int w = 0; w < 3; w++)
        #pragma unroll
        for (int am = 0; am < 2; am++)
            #pragma unroll
            for (int an = 0; an < 4; an++)
                #pragma unroll
                for (int e = 0; e < 4; e++) acc[w][am][an][e] = 0.f;

    auto load_panel = [&](int stage, int k0) {
        uint32_t xs = smem_base + (stage * X_TILE_U32) * 4;
        #pragma unroll
        for (int i = 0; i < 4; i++) {
            cp16(xs + (xrow[i] * XS_STRIDE + xcol4) * 4,
                 X + (size_t)(m0 + xrow[i]) * DD + k0 + xcol4);
        }
        #pragma unroll
        for (int w = 0; w < 3; w++) {
            uint32_t bs = smem_base + (2 * X_TILE_U32 + (stage * 3 + w) * B_TILE_U32) * 4;
            #pragma unroll
            for (int i = 0; i < 2; i++) {
                cp16(bs + (brow[i] * BS_STRIDE + bcol4) * 4,
                     Ws[w] + (size_t)(k0 + brow[i]) * DD + n0 + bcol4);
            }
        }
    };

    uint32_t (*Xsv)[XS_STRIDE] = (uint32_t(*)[XS_STRIDE])smbuf;
    uint32_t (*Bsv)[BS_STRIDE] = (uint32_t(*)[BS_STRIDE])(smbuf + 2 * X_TILE_U32);

    load_panel(0, 0);
    CP_COMMIT();

    const int NP = DD / 32;
    for (int kt = 0; kt < NP; kt++) {
        if (kt + 1 < NP) {
            load_panel((kt + 1) & 1, (kt + 1) * 32);
            CP_COMMIT();
            CP_WAIT(1);
        } else {
            CP_WAIT(0);
        }
        __syncthreads();

        const int st = kt & 1;
        uint32_t (*Xs)[XS_STRIDE] = Xsv + st * 128;
        #pragma unroll
        for (int ks = 0; ks < 32; ks += 8) {
            uint32_t a[2][4];
            #pragma unroll
            for (int am = 0; am < 2; am++) {
                int row = wm * 32 + am * 16;
                a[am][0] = Xs[row + g][ks + t];
                a[am][1] = Xs[row + 8 + g][ks + t];
                a[am][2] = Xs[row + g][ks + t + 4];
                a[am][3] = Xs[row + 8 + g][ks + t + 4];
            }
            #pragma unroll
            for (int w = 0; w < 3; w++) {
                uint32_t (*Bs)[BS_STRIDE] = Bsv + (st * 3 + w) * 32;
                #pragma unroll
                for (int an = 0; an < 4; an++) {
                    int n = wn * 32 + an * 8 + g;
                    uint32_t b0 = Bs[ks + t][n];
                    uint32_t b1 = Bs[ks + t + 4][n];
                    mma_tf32(acc[w][0][an], a[0][0], a[0][1], a[0][2], a[0][3], b0, b1);
                    mma_tf32(acc[w][1][an], a[1][0], a[1][1], a[1][2], a[1][3], b0, b1);
                }
            }
        }
        __syncthreads();
    }

    int mb[2][2], mn[2][2];
    #pragma unroll
    for (int am = 0; am < 2; am++)
        #pragma unroll
        for (int hl = 0; hl < 2; hl++) {
            int m = m0 + wm * 32 + am * 16 + g + hl * 8;
            mb[am][hl] = m / NN;
            mn[am][hl] = m % NN;
        }

    const float* biases[3] = {bq, bk, bv};
    #pragma unroll
    for (int w = 0; w < 3; w++) {
        uint32_t* out = (w == 0) ? g_q : (w == 1) ? g_k : g_v;
        const float* bias = biases[w];
        float scl = (w == 0) ? 0.125f : 1.0f;
        #pragma unroll
        for (int an = 0; an < 4; an++) {
            int col = n0 + wn * 32 + an * 8 + 2 * t;
            int h = col >> 6, dh = col & 63;
            float b0_ = bias[col], b1_ = bias[col + 1];
            #pragma unroll
            for (int am = 0; am < 2; am++)
                #pragma unroll
                for (int hl = 0; hl < 2; hl++) {
                    float v0 = (acc[w][am][an][hl * 2 + 0] + b0_) * scl;
                    float v1 = (acc[w][am][an][hl * 2 + 1] + b1_) * scl;
                    out[((size_t)(h * BB + mb[am][hl]) * NN + mn[am][hl]) * 32 + (dh >> 1)]
                        = f2bf2(v0, v1);
                }
        }
    }
}

// ============================================================
// K3: flash attention, bf16 mma (m16n8k16), sliding-window R chunks,
// cp.async pipelined loads, ldmatrix.trans for V fragments.
// 128 threads (4 warps x 16 rows). smem 71680 B -> 3 blocks/SM.
// ============================================================
__global__ __launch_bounds__(128) void flash_kernel(const int* __restrict__ vl)
{
    extern __shared__ uint32_t fsm[];
    uint32_t* qs = fsm + QS_OFF;
    uint32_t* ks = fsm + KS_OFF;
    uint32_t* pp = fsm + PP_OFF;
    float* Xf0 = (float*)(fsm + X0_OFF);
    float* Xf1 = (float*)(fsm + X1_OFF);

    const uint32_t smem_base = (uint32_t)__cvta_generic_to_shared(fsm);
    const uint32_t ks_b = smem_base + KS_OFF * 4;
    const uint32_t vs_b = smem_base + VS_OFF * 4;
    const uint32_t pp_b = smem_base + PP_OFF * 4;

    const int x = blockIdx.y;
    const int b = x & (BB - 1);
    const int vlen = vl[b];
    const int i0 = blockIdx.x * 64;
    const int base0 = PCLIP - i0;

    const int tid = threadIdx.x;
    const int lane = tid & 31, warp = tid >> 5;
    const int g = lane >> 2, t = lane & 3;
    const int ib = warp * 16;

    const uint32_t* qw = g_q + (size_t)x * NN * 32;
    const uint32_t* kw = g_k + (size_t)x * NN * 32;
    const uint32_t* vw = g_v + (size_t)x * NN * 32;

    // staging coords: 64 rows x 8 chunks(16B) = 512 chunks, 4 per thread
    int strow[4], stw4[4];
    #pragma unroll
    for (int it = 0; it < 4; it++) {
        int idx = tid + it * 128;
        strow[it] = idx >> 3;
        stw4[it] = (idx & 7) * 4;
    }

    // ldmatrix per-lane address components (x4.trans, 16x16 block)
    const int ldrow = (lane & 7) + ((lane >> 3) & 1) * 8;
    const int ldcol = (lane >> 4) & 1;

    // load q tile once (plain LDG.128)
    #pragma unroll
    for (int it = 0; it < 4; it++) {
        int r = strow[it];
        uint4 val = make_uint4(0u, 0u, 0u, 0u);
        if (i0 + r < NN) val = *(const uint4*)(qw + (size_t)(i0 + r) * 32 + stw4[it]);
        qs[r * STKV + stw4[it]]     = val.x; qs[r * STKV + stw4[it] + 1] = val.y;
        qs[r * STKV + stw4[it] + 2] = val.z; qs[r * STKV + stw4[it] + 3] = val.w;
    }

    const int irow0 = i0 + ib + g;
    const int irow1 = irow0 + 8;
    const bool iok0 = irow0 < NN, iok1 = irow1 < NN;
    const int ii0 = ib + g, ii1 = ib + g + 8;

    auto issue_pos = [&](int c) {
        #pragma unroll
        for (int it = 0; it < 4; it++) {
            int r = strow[it];
            int rel = base0 + 64 * c - 63 + r;
            rel = min(max(rel, 0), RLEN - 1);
            cp16(pp_b + (r * STKV + stw4[it]) * 4, g_posbf + (size_t)rel * 32 + stw4[it]);
        }
    };
    auto issue_k = [&](int j0) {
        #pragma unroll
        for (int it = 0; it < 4; it++) {
            int r = strow[it];
            int row = min(j0 + r, NN - 1);
            cp16(ks_b + (r * STKV + stw4[it]) * 4, kw + (size_t)row * 32 + stw4[it]);
        }
    };
    auto issue_v = [&](int j0) {
        #pragma unroll
        for (int it = 0; it < 4; it++) {
            int r = strow[it];
            int row = min(j0 + r, NN - 1);
            cp16(vs_b + (r * STKV + stw4[it]) * 4, vw + (size_t)row * 32 + stw4[it]);
        }
    };

    // R chunk mma: q (qs) x pos (pp), both bf16 K-major, K=64 (4 k16 steps)
    auto r_mma = [&](float tacc[8][4]) {
        #pragma unroll
        for (int fn = 0; fn < 8; fn++)
            #pragma unroll
            for (int e = 0; e < 4; e++) tacc[fn][e] = 0.f;
        #pragma unroll
        for (int kk8 = 0; kk8 < 32; kk8 += 8) {
            uint32_t a0 = qs[(ib + g) * STKV + kk8 + t];
            uint32_t a1 = qs[(ib + 8 + g) * STKV + kk8 + t];
            uint32_t a2 = qs[(ib + g) * STKV + kk8 + t + 4];
            uint32_t a3 = qs[(ib + 8 + g) * STKV + kk8 + t + 4];
            #pragma unroll
            for (int fn = 0; fn < 8; fn++) {
                int n = fn * 8 + g;
                mma_bf16(tacc[fn], a0, a1, a2, a3,
                         pp[n * STKV + kk8 + t], pp[n * STKV + kk8 + t + 4]);
            }
        }
    };

    auto r_store = [&](float* Xf, const float tacc[8][4]) {
        #pragma unroll
        for (int fn = 0; fn < 8; fn++) {
            int c0 = fn * 8 + 2 * t;
            Xf[ii0 * STX + c0]     = tacc[fn][0]; Xf[ii0 * STX + c0 + 1] = tacc[fn][1];
            Xf[ii1 * STX + c0]     = tacc[fn][2]; Xf[ii1 * STX + c0 + 1] = tacc[fn][3];
        }
    };

    // ---- prologue: R chunks 0 and 1; leave Gk(0) in flight ----
    float tacc[8][4];
    issue_pos(0); CP_COMMIT();
    CP_WAIT(0);
    __syncthreads();              // pos0 + qs visible
    r_mma(tacc);
    r_store(Xf0, tacc);
    __syncthreads();
    issue_pos(1); CP_COMMIT();
    issue_k(0);   CP_COMMIT();
    CP_WAIT(1);
    __syncthreads();
    r_mma(tacc);
    r_store(Xf1, tacc);

    float m0 = -1e30f, m1 = -1e30f, l0 = 0.f, l1 = 0.f;
    float oacc[8][4];
    #pragma unroll
    for (int fn = 0; fn < 8; fn++)
        #pragma unroll
        for (int e = 0; e < 4; e++) oacc[fn][e] = 0.f;

    int p = 0;
    for (int jt = 0; 64 * jt < vlen; jt++) {
        const int j0 = 64 * jt;
        CP_WAIT(0);               // Gk(jt) done
        __syncthreads();          // ks visible; pp/vs free
        issue_pos(jt + 2); CP_COMMIT();
        issue_v(j0);       CP_COMMIT();

        // ---- S = q · k^T (bf16) ----
        float sacc[8][4];
        #pragma unroll
        for (int fn = 0; fn < 8; fn++)
            #pragma unroll
            for (int e = 0; e < 4; e++) sacc[fn][e] = 0.f;
        #pragma unroll
        for (int kk8 = 0; kk8 < 32; kk8 += 8) {
            uint32_t a0 = qs[(ib + g) * STKV + kk8 + t];
            uint32_t a1 = qs[(ib + 8 + g) * STKV + kk8 + t];
            uint32_t a2 = qs[(ib + g) * STKV + kk8 + t + 4];
            uint32_t a3 = qs[(ib + 8 + g) * STKV + kk8 + t + 4];
            #pragma unroll
            for (int fn = 0; fn < 8; fn++) {
                int n = fn * 8 + g;
                mma_bf16(sacc[fn], a0, a1, a2, a3,
                         ks[n * STKV + kk8 + t], ks[n * STKV + kk8 + t + 4]);
            }
        }

        CP_WAIT(1);               // Gpos done (Gv in flight)
        __syncthreads();          // pos visible; all warps done reading ks
        issue_k(j0 + 64); CP_COMMIT();

        // ---- Rnew = chunk(jt+2) ----
        r_mma(tacc);

        CP_WAIT(1);               // Gv done (Gk in flight)
        __syncthreads();          // vs visible; all warps done reading pp

        // ---- gather bias; mask; tile row max ----
        float* Af = p ? Xf1 : Xf0;
        float* Bf = p ? Xf0 : Xf1;
        float tm0 = -1e30f, tm1 = -1e30f;
        #pragma unroll
        for (int fn = 0; fn < 8; fn++) {
            int jj = fn * 8 + 2 * t;
            int j = j0 + jj;
            int d00 = jj - ii0;
            int d10 = jj - ii1;
            float r00 = (d00 > 0)     ? Bf[ii0 * STX + d00 - 1] : Af[ii0 * STX + d00 + 63];
            float r01 = (d00 + 1 > 0) ? Bf[ii0 * STX + d00]     : Af[ii0 * STX + d00 + 64];
            float r10 = (d10 > 0)     ? Bf[ii1 * STX + d10 - 1] : Af[ii1 * STX + d10 + 63];
            float r11 = (d10 + 1 > 0) ? Bf[ii1 * STX + d10]     : Af[ii1 * STX + d10 + 64];
            sacc[fn][0] = (j < vlen)     ? sacc[fn][0] + r00 : -1e30f;
            sacc[fn][1] = (j + 1 < vlen) ? sacc[fn][1] + r01 : -1e30f;
            sacc[fn][2] = (j < vlen)     ? sacc[fn][2] + r10 : -1e30f;
            sacc[fn][3] = (j + 1 < vlen) ? sacc[fn][3] + r11 : -1e30f;
            tm0 = fmaxf(tm0, fmaxf(sacc[fn][0], sacc[fn][1]));
            tm1 = fmaxf(tm1, fmaxf(sacc[fn][2], sacc[fn][3]));
        }
        tm0 = fmaxf(tm0, __shfl_xor_sync(0xffffffffu, tm0, 1));
        tm0 = fmaxf(tm0, __shfl_xor_sync(0xffffffffu, tm0, 2));
        tm1 = fmaxf(tm1, __shfl_xor_sync(0xffffffffu, tm1, 1));
        tm1 = fmaxf(tm1, __shfl_xor_sync(0xffffffffu, tm1, 2));

        float mn0 = fmaxf(m0, tm0), mn1 = fmaxf(m1, tm1);
        float sc0 = __expf(m0 - mn0), sc1 = __expf(m1 - mn1);
        m0 = mn0; m1 = mn1;

        // ---- exp, stage P into pp (bf16x2), row sums ----
        float tl0 = 0.f, tl1 = 0.f;
        #pragma unroll
        for (int fn = 0; fn < 8; fn++) {
            float p00 = __expf(sacc[fn][0] - mn0);
            float p01 = __expf(sacc[fn][1] - mn0);
            float p10 = __expf(sacc[fn][2] - mn1);
            float p11 = __expf(sacc[fn][3] - mn1);
            tl0 += p00 + p01; tl1 += p10 + p11;
            int wd = fn * 4 + t;
            pp[ii0 * STKV + wd] = f2bf2(p00, p01);
            pp[ii1 * STKV + wd] = f2bf2(p10, p11);
        }
        tl0 += __shfl_xor_sync(0xffffffffu, tl0, 1);
        tl0 += __shfl_xor_sync(0xffffffffu, tl0, 2);
        tl1 += __shfl_xor_sync(0xffffffffu, tl1, 1);
        tl1 += __shfl_xor_sync(0xffffffffu, tl1, 2);
        l0 = l0 * sc0 + tl0;
        l1 = l1 * sc1 + tl1;

        #pragma unroll
        for (int fn = 0; fn < 8; fn++) {
            oacc[fn][0] *= sc0; oacc[fn][1] *= sc0;
            oacc[fn][2] *= sc1; oacc[fn][3] *= sc1;
        }

        __syncwarp();             // P visible within warp; gather reads done

        r_store(Af, tacc);        // retire old chunk
        p ^= 1;

        // ---- O += P · V (A from pp, B via ldmatrix.trans on vs) ----
        #pragma unroll
        for (int kk8 = 0; kk8 < 32; kk8 += 8) {
            int kj = kk8 * 2;     // j base of this k16 chunk (rows of V)
            uint32_t a0 = pp[(ib + g) * STKV + kk8 + t];
            uint32_t a1 = pp[(ib + 8 + g) * STKV + kk8 + t];
            uint32_t a2 = pp[(ib + g) * STKV + kk8 + t + 4];
            uint32_t a3 = pp[(ib + 8 + g) * STKV + kk8 + t + 4];
            #pragma unroll
            for (int fn = 0; fn < 8; fn += 2) {
                uint32_t addr = vs_b + (((kj + ldrow) * STKV) + (fn + ldcol) * 4) * 4;
                uint32_t b0, b1, b2, b3;
                asm volatile(
                    "ldmatrix.sync.aligned.m8n8.x4.trans.shared.b16 {%0,%1,%2,%3}, [%4];\n"
                    : "=r"(b0), "=r"(b1), "=r"(b2), "=r"(b3) : "r"(addr));
                mma_bf16(oacc[fn],     a0, a1, a2, a3, b0, b1);
                mma_bf16(oacc[fn + 1], a0, a1, a2, a3, b2, b3);
            }
        }
        __syncwarp();
    }
    CP_WAIT(0);                   // drain trailing Gk

    float inv0 = 1.f / l0, inv1 = 1.f / l1;
    float* ob = g_ao + (size_t)x * NN * DHE;
    #pragma unroll
    for (int fn = 0; fn < 8; fn++) {
        int dh = fn * 8 + 2 * t;
        if (iok0) {
            float2 v;
            v.x = __uint_as_float(f2tf(oacc[fn][0] * inv0));
            v.y = __uint_as_float(f2tf(oacc[fn][1] * inv0));
            *(float2*)(ob + (size_t)irow0 * DHE + dh) = v;
        }
        if (iok1) {
            float2 v;
            v.x = __uint_as_float(f2tf(oacc[fn][2] * inv1));
            v.y = __uint_as_float(f2tf(oacc[fn][3] * inv1));
            *(float2*)(ob + (size_t)irow1 * DHE + dh) = v;
        }
    }
}

// ============================================================
// K5: output projection, tf32, cp.async 2-stage, block 128x128.
// ============================================================
__global__ __launch_bounds__(256) void outproj_gemm(const float* __restrict__ W,
                                                    const float* __restrict__ bias,
                                                    const float* __restrict__ query)
{
    extern __shared__ uint32_t smbuf[];
    const uint32_t smem_base = (uint32_t)__cvta_generic_to_shared(smbuf);

    const int tid = threadIdx.x;
    const int lane = tid & 31, warp = tid >> 5;
    const int g = lane >> 2, t = lane & 3;
    const int wm = warp >> 1, wn = warp & 1;
    const int m0 = blockIdx.x * 128;
    const int n0 = blockIdx.y * 128;

    const int xrow[4] = { (tid) >> 3, (tid + 256) >> 3, (tid + 512) >> 3, (tid + 768) >> 3 };
    const int xcol4 = (tid & 7) * 4;
    const int brow[4] = { tid >> 5, (tid + 256) >> 5, (tid + 512) >> 5, (tid + 768) >> 5 };
    const int bcol4 = (tid & 31) * 4;

    size_t pre[4];
    #pragma unroll
    for (int i = 0; i < 4; i++) {
        int m = m0 + xrow[i];
        int bb = m / NN, nn = m % NN;
        pre[i] = ((size_t)bb * NN + nn) * DHE;
    }

    float acc[2][8][4];
    #pragma unroll
    for (int am = 0; am < 2; am++)
        #pragma unroll
        for (int an = 0; an < 8; an++)
            #pragma unroll
            for (int e = 0; e < 4; e++) acc[am][an][e] = 0.f;

    auto load_panel = [&](int stage, int kt) {
        const int h = kt >> 1;
        const int dh0 = (kt & 1) * 32;
        const size_t hoff = (size_t)h * BB * NN * DHE;
        uint32_t xs = smem_base + (stage * X_TILE_U32) * 4;
        #pragma unroll
        for (int i = 0; i < 4; i++) {
            cp16(xs + (xrow[i] * XS_STRIDE + xcol4) * 4,
                 g_ao + hoff + pre[i] + dh0 + xcol4);
        }
        uint32_t bs = smem_base + (2 * X_TILE_U32 + stage * OB_TILE_U32) * 4;
        #pragma unroll
        for (int i = 0; i < 4; i++) {
            cp16(bs + (brow[i] * OBS_STRIDE + bcol4) * 4,
                 W + (size_t)(kt * 32 + brow[i]) * DD + n0 + bcol4);
        }
    };

    uint32_t (*Xsv)[XS_STRIDE] = (uint32_t(*)[XS_STRIDE])smbuf;
    uint32_t (*Bsv)[OBS_STRIDE] = (uint32_t(*)[OBS_STRIDE])(smbuf + 2 * X_TILE_U32);

    load_panel(0, 0);
    CP_COMMIT();

    const int NP = DD / 32;
    for (int kt = 0; kt < NP; kt++) {
        if (kt + 1 < NP) {
            load_panel((kt + 1) & 1, kt + 1);
            CP_COMMIT();
            CP_WAIT(1);
        } else {
            CP_WAIT(0);
        }
        __syncthreads();

        const int st = kt & 1;
        uint32_t (*Xs)[XS_STRIDE] = Xsv + st * 128;
        uint32_t (*Bs)[OBS_STRIDE] = Bsv + st * 32;
        #pragma unroll
        for (int ks = 0; ks < 32; ks += 8) {
            uint32_t a[2][4];
            #pragma unroll
            for (int am = 0; am < 2; am++) {
                int row = wm * 32 + am * 16;
                a[am][0] = Xs[row + g][ks + t];
                a[am][1] = Xs[row + 8 + g][ks + t];
                a[am][2] = Xs[row + g][ks + t + 4];
                a[am][3] = Xs[row + 8 + g][ks + t + 4];
            }
            #pragma unroll
            for (int an = 0; an < 8; an++) {
                int n = wn * 64 + an * 8 + g;
                uint32_t b0 = Bs[ks + t][n];
                uint32_t b1 = Bs[ks + t + 4][n];
                mma_tf32(acc[0][an], a[0][0], a[0][1], a[0][2], a[0][3], b0, b1);
                mma_tf32(acc[1][an], a[1][0], a[1][1], a[1][2], a[1][3], b0, b1);
            }
        }
        __syncthreads();
    }

    #pragma unroll
    for (int an = 0; an < 8; an++) {
        int col = n0 + wn * 64 + an * 8 + 2 * t;
        #pragma unroll
        for (int cc = 0; cc < 2; cc++) {
            int e = col + cc;
            float bv_ = bias[e];
            #pragma unroll
            for (int am = 0; am < 2; am++)
                #pragma unroll
                for (int hl = 0; hl < 2; hl++) {
                    int m = m0 + wm * 32 + am * 16 + g + hl * 8;
                    g_o[(size_t)m * DD + e] =
                        acc[am][an][hl * 2 + cc] + bv_ + query[(size_t)m * DD + e];
                }
        }
    }
}

// ============================================================
// K6: LayerNorm over D=512 per row -> d_out
// ============================================================
__global__ __launch_bounds__(256) void ln_kernel(const float* __restrict__ gamma,
                                                 const float* __restrict__ beta,
                                                 float* __restrict__ out)
{
    const int m = blockIdx.x;
    const float* xr = g_o + (size_t)m * DD;
    const int tid = threadIdx.x;

    __shared__ float red[8];

    float x0 = xr[tid], x1 = xr[tid + 256];
    float s = x0 + x1;
    #pragma unroll
    for (int off = 16; off > 0; off >>= 1)
        s += __shfl_xor_sync(0xffffffff, s, off);
    if ((tid & 31) == 0) red[tid >> 5] = s;
    __syncthreads();
    float tot = 0.f;
    #pragma unroll
    for (int w = 0; w < 8; w++) tot += red[w];
    float mean = tot * (1.f / DD);

    float d0 = x0 - mean, d1 = x1 - mean;
    float ss = d0 * d0 + d1 * d1;
    #pragma unroll
    for (int off = 16; off > 0; off >>= 1)
        ss += __shfl_xor_sync(0xffffffff, ss, off);
    __syncthreads();
    if ((tid & 31) == 0) red[tid >> 5] = ss;
    __syncthreads();
    float tss = 0.f;
    #pragma unroll
    for (int w = 0; w < 8; w++) tss += red[w];
    float var = tss * (1.f / DD);
    float rstd = rsqrtf(var + 1e-7f);

    out[(size_t)m * DD + tid]       = gamma[tid]       * d0 * rstd + beta[tid];
    out[(size_t)m * DD + tid + 256] = gamma[tid + 256] * d1 * rstd + beta[tid + 256];
}

// ============================================================
extern "C" void kernel_launch(void* const* d_in, const int* in_sizes, int n_in,
                              void* d_out, int out_size)
{
    const float* query = (const float*)d_in[0];
    const float* Wq    = (const float*)d_in[1];
    const float* bq    = (const float*)d_in[2];
    const float* Wk    = (const float*)d_in[3];
    const float* bk    = (const float*)d_in[4];
    const float* Wv    = (const float*)d_in[5];
    const float* bv    = (const float*)d_in[6];
    const float* Wh    = (const float*)d_in[7];
    const float* bh    = (const float*)d_in[8];
    const float* pos_k = (const float*)d_in[9];
    const float* gamma = (const float*)d_in[10];
    const float* beta  = (const float*)d_in[11];
    const int*   vl    = (const int*)d_in[12];
    float* out = (float*)d_out;

    const int FLASH_SMEM = FLASH_U32 * 4;                           // 71680 B
    const int QKV_SMEM   = (2 * X_TILE_U32 + 6 * B_TILE_U32) * 4;   // 89088 B
    const int OUT_SMEM   = (2 * X_TILE_U32 + 2 * OB_TILE_U32) * 4;  // 70656 B

    static int smem_set = 0;
    if (!smem_set) {
        cudaFuncSetAttribute(flash_kernel,
                             cudaFuncAttributeMaxDynamicSharedMemorySize, FLASH_SMEM);
        cudaFuncSetAttribute(qkv_fused,
                             cudaFuncAttributeMaxDynamicSharedMemorySize, QKV_SMEM);
        cudaFuncSetAttribute(outproj_gemm,
                             cudaFuncAttributeMaxDynamicSharedMemorySize, OUT_SMEM);
        smem_set = 1;
    }

    pos2bf_kernel<<<(RLEN * 32 + 255) / 256, 256>>>(pos_k);
    qkv_fused<<<dim3(BN / 128, DD / 64), 256, QKV_SMEM>>>(query, Wq, bq, Wk, bk, Wv, bv);

    flash_kernel<<<dim3(9, HB), 128, FLASH_SMEM>>>(vl);

    outproj_gemm<<<dim3(BN / 128, DD / 128), 256, OUT_SMEM>>>(Wh, bh, query);
    ln_kernel<<<BN, 256>>>(gamma, beta, out);
}

// round 10
// speedup vs baseline: 1.1836x; 1.1836x over previous
#include <cuda_runtime.h>
#include <cstdint>
#include <math.h>

#define BB 32
#define NN 540
#define DD 512
#define HH 8
#define DHE 64
#define HB (HH*BB)          // 256
#define BN (BB*NN)          // 17280
#define PCLIP 539
#define RLEN (2*PCLIP+1)    // 1079

// -------- scratch (device globals) --------
__device__ float g_q[(size_t)HB*NN*DHE];   // tf32 bits, q pre-scaled by 0.125
__device__ float g_k[(size_t)HB*NN*DHE];   // tf32 bits
__device__ float g_v[(size_t)HB*NN*DHE];   // tf32 bits
__device__ float g_ao[(size_t)HB*NN*DHE];  // attn@v, tf32 bits, head-major
__device__ float g_o[(size_t)BN*DD];       // pre-LN (fp32)

// -------- helpers --------
__device__ __forceinline__ uint32_t f2tf(float f) {
    uint32_t u;
    asm("cvt.rna.tf32.f32 %0, %1;" : "=r"(u) : "f"(f));
    return u;
}

__device__ __forceinline__ void mma_tf32(float c[4],
                                         uint32_t a0, uint32_t a1, uint32_t a2, uint32_t a3,
                                         uint32_t b0, uint32_t b1) {
    asm volatile(
        "mma.sync.aligned.m16n8k8.row.col.f32.tf32.tf32.f32 "
        "{%0,%1,%2,%3}, {%4,%5,%6,%7}, {%8,%9}, {%0,%1,%2,%3};\n"
        : "+f"(c[0]), "+f"(c[1]), "+f"(c[2]), "+f"(c[3])
        : "r"(a0), "r"(a1), "r"(a2), "r"(a3), "r"(b0), "r"(b1));
}

__device__ __forceinline__ void cp16(uint32_t smem_u32_addr, const void* gptr) {
    asm volatile("cp.async.cg.shared.global [%0], [%1], 16;\n"
                 :: "r"(smem_u32_addr), "l"(gptr));
}
#define CP_COMMIT() asm volatile("cp.async.commit_group;\n" ::)
#define CP_WAIT(n)  asm volatile("cp.async.wait_group %0;\n" :: "n"(n))

// smem tiling constants for pipelined GEMMs
#define XS_STRIDE 36
#define X_TILE_U32 (128*XS_STRIDE)     // 4608
#define BS_STRIDE 68
#define B_TILE_U32 (32*BS_STRIDE)      // 2176

// ============================================================
// K1: fused QKV projection, tf32 mma, cp.async 2-stage pipeline.
// ============================================================
__global__ __launch_bounds__(256) void qkv_fused(const float* __restrict__ X,
                                                 const float* __restrict__ Wq, const float* __restrict__ bq,
                                                 const float* __restrict__ Wk, const float* __restrict__ bk,
                                                 const float* __restrict__ Wv, const float* __restrict__ bv)
{
    extern __shared__ uint32_t smbuf[];
    const uint32_t smem_base = (uint32_t)__cvta_generic_to_shared(smbuf);

    const int tid = threadIdx.x;
    const int lane = tid & 31, warp = tid >> 5;
    const int g = lane >> 2, t = lane & 3;
    const int wm = warp >> 1, wn = warp & 1;
    const int m0 = blockIdx.x * 128;
    const int n0 = blockIdx.y * 64;

    const float* Ws[3] = {Wq, Wk, Wv};

    const int xrow[4] = { (tid) >> 3, (tid + 256) >> 3, (tid + 512) >> 3, (tid + 768) >> 3 };
    const int xcol4 = (tid & 7) * 4;
    const int brow[2] = { tid >> 4, (tid + 256) >> 4 };
    const int bcol4 = (tid & 15) * 4;

    float acc[3][2][4][4];
    #pragma unroll
    for (int w = 0; w < 3; w++)
        #pragma unroll
        for (int am = 0; am < 2; am++)
            #pragma unroll
            for (int an = 0; an < 4; an++)
                #pragma unroll
                for (int e = 0; e < 4; e++) acc[w][am][an][e] = 0.f;

    auto load_panel = [&](int stage, int k0) {
        uint32_t xs = smem_base + (stage * X_TILE_U32) * 4;
        #pragma unroll
        for (int i = 0; i < 4; i++) {
            cp16(xs + (xrow[i] * XS_STRIDE + xcol4) * 4,
                 X + (size_t)(m0 + xrow[i]) * DD + k0 + xcol4);
        }
        #pragma unroll
        for (int w = 0; w < 3; w++) {
            uint32_t bs = smem_base + (2 * X_TILE_U32 + (stage * 3 + w) * B_TILE_U32) * 4;
            #pragma unroll
            for (int i = 0; i < 2; i++) {
                cp16(bs + (brow[i] * BS_STRIDE + bcol4) * 4,
                     Ws[w] + (size_t)(k0 + brow[i]) * DD + n0 + bcol4);
            }
        }
    };

    uint32_t (*Xsv)[XS_STRIDE] = (uint32_t(*)[XS_STRIDE])smbuf;
    uint32_t (*Bsv)[BS_STRIDE] = (uint32_t(*)[BS_STRIDE])(smbuf + 2 * X_TILE_U32);

    load_panel(0, 0);
    CP_COMMIT();

    const int NP = DD / 32;
    for (int kt = 0; kt < NP; kt++) {
        if (kt + 1 < NP) {
            load_panel((kt + 1) & 1, (kt + 1) * 32);
            CP_COMMIT();
            CP_WAIT(1);
        } else {
            CP_WAIT(0);
        }
        __syncthreads();

        const int st = kt & 1;
        uint32_t (*Xs)[XS_STRIDE] = Xsv + st * 128;
        #pragma unroll
        for (int ks = 0; ks < 32; ks += 8) {
            uint32_t a[2][4];
            #pragma unroll
            for (int am = 0; am < 2; am++) {
                int row = wm * 32 + am * 16;
                a[am][0] = Xs[row + g][ks + t];
                a[am][1] = Xs[row + 8 + g][ks + t];
                a[am][2] = Xs[row + g][ks + t + 4];
                a[am][3] = Xs[row + 8 + g][ks + t + 4];
            }
            #pragma unroll
            for (int w = 0; w < 3; w++) {
                uint32_t (*Bs)[BS_STRIDE] = Bsv + (st * 3 + w) * 32;
                #pragma unroll
                for (int an = 0; an < 4; an++) {
                    int n = wn * 32 + an * 8 + g;
                    uint32_t b0 = Bs[ks + t][n];
                    uint32_t b1 = Bs[ks + t + 4][n];
                    mma_tf32(acc[w][0][an], a[0][0], a[0][1], a[0][2], a[0][3], b0, b1);
                    mma_tf32(acc[w][1][an], a[1][0], a[1][1], a[1][2], a[1][3], b0, b1);
                }
            }
        }
        __syncthreads();
    }

    int mb[2][2], mn[2][2];
    #pragma unroll
    for (int am = 0; am < 2; am++)
        #pragma unroll
        for (int hl = 0; hl < 2; hl++) {
            int m = m0 + wm * 32 + am * 16 + g + hl * 8;
            mb[am][hl] = m / NN;
            mn[am][hl] = m % NN;
        }

    const float* biases[3] = {bq, bk, bv};
    #pragma unroll
    for (int w = 0; w < 3; w++) {
        float* out = (w == 0) ? g_q : (w == 1) ? g_k : g_v;
        const float* bias = biases[w];
        float scl = (w == 0) ? 0.125f : 1.0f;
        #pragma unroll
        for (int an = 0; an < 4; an++) {
            int col = n0 + wn * 32 + an * 8 + 2 * t;
            #pragma unroll
            for (int cc = 0; cc < 2; cc++) {
                int e = col + cc;
                int h = e >> 6, dh = e & 63;
                float bv_ = bias[e];
                #pragma unroll
                for (int am = 0; am < 2; am++)
                    #pragma unroll
                    for (int hl = 0; hl < 2; hl++) {
                        float val = (acc[w][am][an][hl * 2 + cc] + bv_) * scl;
                        out[((size_t)(h * BB + mb[am][hl]) * NN + mn[am][hl]) * DHE + dh]
                            = __uint_as_float(f2tf(val));
                    }
            }
        }
    }
}

// ============================================================
// K3: flash attention, sliding-window R chunks + cp.async pipelined
// k/v/pos loads (split commit groups; k prefetched a full iter ahead).
// 128 threads (4 warps x 16 rows). smem: 6 x 64x68 u32 = 104448 B.
// ============================================================
__global__ __launch_bounds__(128) void flash_kernel(const float* __restrict__ pos_k,
                                                    const int* __restrict__ vl)
{
    extern __shared__ uint32_t fsm[];
    uint32_t (*qs)[68] = (uint32_t(*)[68])fsm;
    uint32_t (*ks)[68] = (uint32_t(*)[68])(fsm + 4352);
    uint32_t (*vs)[68] = (uint32_t(*)[68])(fsm + 2 * 4352);
    uint32_t (*pp)[68] = (uint32_t(*)[68])(fsm + 3 * 4352);   // pos chunk, then P
    float (*Xf0)[68] = (float(*)[68])(fsm + 4 * 4352);        // R ping
    float (*Xf1)[68] = (float(*)[68])(fsm + 5 * 4352);        // R pong

    const uint32_t smem_base = (uint32_t)__cvta_generic_to_shared(fsm);
    const uint32_t ks_base = smem_base + 4352 * 4;
    const uint32_t vs_base = smem_base + 2 * 4352 * 4;
    const uint32_t pp_base = smem_base + 3 * 4352 * 4;

    const int x = blockIdx.y;
    const int b = x & (BB - 1);
    const int vlen = vl[b];
    const int i0 = blockIdx.x * 64;
    const int base0 = PCLIP - i0;    // rel at (j=0, i=i0)

    const int tid = threadIdx.x;
    const int lane = tid & 31, warp = tid >> 5;
    const int g = lane >> 2, t = lane & 3;
    const int ib = warp * 16;

    const float* qb = g_q + (size_t)x * NN * DHE;
    const float* kb = g_k + (size_t)x * NN * DHE;
    const float* vb = g_v + (size_t)x * NN * DHE;

    // per-thread staging coords: 8 chunks of (row, col4)
    const int lrow[8] = { tid >> 4, (tid + 128) >> 4, (tid + 256) >> 4, (tid + 384) >> 4,
                          (tid + 512) >> 4, (tid + 640) >> 4, (tid + 768) >> 4, (tid + 896) >> 4 };
    const int lc4 = (tid & 15) * 4;

    // load q tile once (plain LDG.128)
    #pragma unroll
    for (int it = 0; it < 8; it++) {
        int r = lrow[it];
        uint4 val = make_uint4(0u, 0u, 0u, 0u);
        if (i0 + r < NN) val = *(const uint4*)(qb + (size_t)(i0 + r) * DHE + lc4);
        qs[r][lc4] = val.x; qs[r][lc4 + 1] = val.y; qs[r][lc4 + 2] = val.z; qs[r][lc4 + 3] = val.w;
    }

    const int irow0 = i0 + ib + g;
    const int irow1 = irow0 + 8;
    const bool iok0 = irow0 < NN, iok1 = irow1 < NN;
    const int ii0 = ib + g, ii1 = ib + g + 8;

    // cp.async issuers (clamped addresses; stale/garbage rows only feed masked lanes)
    auto issue_pos = [&](int c) {
        #pragma unroll
        for (int it = 0; it < 8; it++) {
            int r = lrow[it];
            int rel = base0 + 64 * c - 63 + r;
            rel = min(max(rel, 0), RLEN - 1);
            cp16(pp_base + (r * 68 + lc4) * 4, pos_k + (size_t)rel * DHE + lc4);
        }
    };
    auto issue_k = [&](int j0) {
        #pragma unroll
        for (int it = 0; it < 8; it++) {
            int r = lrow[it];
            int row = min(j0 + r, NN - 1);
            cp16(ks_base + (r * 68 + lc4) * 4, kb + (size_t)row * DHE + lc4);
        }
    };
    auto issue_v = [&](int j0) {
        #pragma unroll
        for (int it = 0; it < 8; it++) {
            int r = lrow[it];
            int row = min(j0 + r, NN - 1);
            cp16(vs_base + (r * 68 + lc4) * 4, vb + (size_t)row * DHE + lc4);
        }
    };

    // R chunk mma (reads qs + pp) into tacc
    auto r_mma = [&](float tacc[8][4]) {
        #pragma unroll
        for (int fn = 0; fn < 8; fn++)
            #pragma unroll
            for (int e = 0; e < 4; e++) tacc[fn][e] = 0.f;
        #pragma unroll
        for (int kk = 0; kk < 64; kk += 8) {
            uint32_t a0 = qs[ib + g][kk + t];
            uint32_t a1 = qs[ib + 8 + g][kk + t];
            uint32_t a2 = qs[ib + g][kk + t + 4];
            uint32_t a3 = qs[ib + 8 + g][kk + t + 4];
            #pragma unroll
            for (int fn = 0; fn < 8; fn++) {
                int n = fn * 8 + g;
                mma_tf32(tacc[fn], a0, a1, a2, a3, pp[n][kk + t], pp[n][kk + t + 4]);
            }
        }
    };

    auto r_store = [&](float (*Xf)[68], const float tacc[8][4]) {
        #pragma unroll
        for (int fn = 0; fn < 8; fn++) {
            int c0 = fn * 8 + 2 * t;
            Xf[ii0][c0]     = tacc[fn][0]; Xf[ii0][c0 + 1] = tacc[fn][1];
            Xf[ii1][c0]     = tacc[fn][2]; Xf[ii1][c0 + 1] = tacc[fn][3];
        }
    };

    // ---- prologue: R chunks 0 and 1; leave Gk(0) in flight ----
    float tacc[8][4];
    issue_pos(0); CP_COMMIT();
    CP_WAIT(0);
    __syncthreads();              // pos0 + qs visible
    r_mma(tacc);
    r_store(Xf0, tacc);
    __syncthreads();              // all warps done reading pp
    issue_pos(1); CP_COMMIT();    // Gpos1
    issue_k(0);   CP_COMMIT();    // Gk(0)
    CP_WAIT(1);                   // pos1 done, k0 in flight
    __syncthreads();
    r_mma(tacc);
    r_store(Xf1, tacc);

    float m0 = -1e30f, m1 = -1e30f, l0 = 0.f, l1 = 0.f;
    float oacc[8][4];
    #pragma unroll
    for (int fn = 0; fn < 8; fn++)
        #pragma unroll
        for (int e = 0; e < 4; e++) oacc[fn][e] = 0.f;

    int p = 0;
    for (int jt = 0; 64 * jt < vlen; jt++) {
        const int j0 = 64 * jt;
        CP_WAIT(0);               // Gk(jt) done
        __syncthreads();          // ks visible; pp/vs free (prev readers done)
        issue_pos(jt + 2); CP_COMMIT();   // Gpos
        issue_v(j0);       CP_COMMIT();   // Gv

        // ---- S = q · k^T (ks prefetched) ----
        float sacc[8][4];
        #pragma unroll
        for (int fn = 0; fn < 8; fn++)
            #pragma unroll
            for (int e = 0; e < 4; e++) sacc[fn][e] = 0.f;
        #pragma unroll
        for (int kk = 0; kk < 64; kk += 8) {
            uint32_t a0 = qs[ib + g][kk + t];
            uint32_t a1 = qs[ib + 8 + g][kk + t];
            uint32_t a2 = qs[ib + g][kk + t + 4];
            uint32_t a3 = qs[ib + 8 + g][kk + t + 4];
            #pragma unroll
            for (int fn = 0; fn < 8; fn++) {
                int n = fn * 8 + g;
                mma_tf32(sacc[fn], a0, a1, a2, a3, ks[n][kk + t], ks[n][kk + t + 4]);
            }
        }

        CP_WAIT(1);               // Gpos done (Gv in flight)
        __syncthreads();          // pos visible; all warps done reading ks
        issue_k(j0 + 64); CP_COMMIT();    // Gk(jt+1) — full iteration to land

        // ---- Rnew = chunk(jt+2) (reads pp) ----
        r_mma(tacc);

        CP_WAIT(1);               // Gv done (Gk in flight)
        __syncthreads();          // vs visible; all warps done reading pp

        // ---- gather bias from A=X[p] (d<=0), B=X[p^1] (d>0); mask; max ----
        float (*Af)[68] = p ? Xf1 : Xf0;
        float (*Bf)[68] = p ? Xf0 : Xf1;
        float tm0 = -1e30f, tm1 = -1e30f;
        #pragma unroll
        for (int fn = 0; fn < 8; fn++) {
            int jj = fn * 8 + 2 * t;
            int j = j0 + jj;
            int d00 = jj - ii0;
            int d10 = jj - ii1;
            float r00 = (d00 > 0)     ? Bf[ii0][d00 - 1] : Af[ii0][d00 + 63];
            float r01 = (d00 + 1 > 0) ? Bf[ii0][d00]     : Af[ii0][d00 + 64];
            float r10 = (d10 > 0)     ? Bf[ii1][d10 - 1] : Af[ii1][d10 + 63];
            float r11 = (d10 + 1 > 0) ? Bf[ii1][d10]     : Af[ii1][d10 + 64];
            sacc[fn][0] = (j < vlen)     ? sacc[fn][0] + r00 : -1e30f;
            sacc[fn][1] = (j + 1 < vlen) ? sacc[fn][1] + r01 : -1e30f;
            sacc[fn][2] = (j < vlen)     ? sacc[fn][2] + r10 : -1e30f;
            sacc[fn][3] = (j + 1 < vlen) ? sacc[fn][3] + r11 : -1e30f;
            tm0 = fmaxf(tm0, fmaxf(sacc[fn][0], sacc[fn][1]));
            tm1 = fmaxf(tm1, fmaxf(sacc[fn][2], sacc[fn][3]));
        }
        tm0 = fmaxf(tm0, __shfl_xor_sync(0xffffffffu, tm0, 1));
        tm0 = fmaxf(tm0, __shfl_xor_sync(0xffffffffu, tm0, 2));
        tm1 = fmaxf(tm1, __shfl_xor_sync(0xffffffffu, tm1, 1));
        tm1 = fmaxf(tm1, __shfl_xor_sync(0xffffffffu, tm1, 2));

        float mn0 = fmaxf(m0, tm0), mn1 = fmaxf(m1, tm1);
        float sc0 = __expf(m0 - mn0), sc1 = __expf(m1 - mn1);
        m0 = mn0; m1 = mn1;

        // ---- exp, stage P into pp (tf32), row sums ----
        float tl0 = 0.f, tl1 = 0.f;
        #pragma unroll
        for (int fn = 0; fn < 8; fn++) {
            float p00 = __expf(sacc[fn][0] - mn0);
            float p01 = __expf(sacc[fn][1] - mn0);
            float p10 = __expf(sacc[fn][2] - mn1);
            float p11 = __expf(sacc[fn][3] - mn1);
            tl0 += p00 + p01; tl1 += p10 + p11;
            int c0 = fn * 8 + 2 * t;
            pp[ii0][c0]     = f2tf(p00);
            pp[ii0][c0 + 1] = f2tf(p01);
            pp[ii1][c0]     = f2tf(p10);
            pp[ii1][c0 + 1] = f2tf(p11);
        }
        tl0 += __shfl_xor_sync(0xffffffffu, tl0, 1);
        tl0 += __shfl_xor_sync(0xffffffffu, tl0, 2);
        tl1 += __shfl_xor_sync(0xffffffffu, tl1, 1);
        tl1 += __shfl_xor_sync(0xffffffffu, tl1, 2);
        l0 = l0 * sc0 + tl0;
        l1 = l1 * sc1 + tl1;

        #pragma unroll
        for (int fn = 0; fn < 8; fn++) {
            oacc[fn][0] *= sc0; oacc[fn][1] *= sc0;
            oacc[fn][2] *= sc1; oacc[fn][3] *= sc1;
        }

        __syncwarp();             // P visible within warp; gather reads done

        r_store(Af, tacc);        // retire old chunk
        p ^= 1;

        // ---- O += P · V ----
        #pragma unroll
        for (int kk = 0; kk < 64; kk += 8) {
            uint32_t a0 = pp[ib + g][kk + t];
            uint32_t a1 = pp[ib + 8 + g][kk + t];
            uint32_t a2 = pp[ib + g][kk + t + 4];
            uint32_t a3 = pp[ib + 8 + g][kk + t + 4];
            #pragma unroll
            for (int fn = 0; fn < 8; fn++) {
                int n = fn * 8 + g;
                mma_tf32(oacc[fn], a0, a1, a2, a3, vs[kk + t][n], vs[kk + t + 4][n]);
            }
        }
        __syncwarp();
    }
    CP_WAIT(0);                   // drain trailing Gk

    float inv0 = 1.f / l0, inv1 = 1.f / l1;
    float* ob = g_ao + (size_t)x * NN * DHE;
    #pragma unroll
    for (int fn = 0; fn < 8; fn++) {
        int dh = fn * 8 + 2 * t;
        if (iok0) {
            float2 v;
            v.x = __uint_as_float(f2tf(oacc[fn][0] * inv0));
            v.y = __uint_as_float(f2tf(oacc[fn][1] * inv0));
            *(float2*)(ob + (size_t)irow0 * DHE + dh) = v;
        }
        if (iok1) {
            float2 v;
            v.x = __uint_as_float(f2tf(oacc[fn][2] * inv1));
            v.y = __uint_as_float(f2tf(oacc[fn][3] * inv1));
            *(float2*)(ob + (size_t)irow1 * DHE + dh) = v;
        }
    }
}

// ============================================================
// K5: output projection, cp.async 2-stage pipeline, block tile 128x64
// (reverted from 128x128: measured 100us vs 143us — reg-pressure capped).
// ============================================================
__global__ __launch_bounds__(256) void outproj_gemm(const float* __restrict__ W,
                                                    const float* __restrict__ bias,
                                                    const float* __restrict__ query)
{
    extern __shared__ uint32_t smbuf[];
    const uint32_t smem_base = (uint32_t)__cvta_generic_to_shared(smbuf);

    const int tid = threadIdx.x;
    const int lane = tid & 31, warp = tid >> 5;
    const int g = lane >> 2, t = lane & 3;
    const int wm = warp >> 1, wn = warp & 1;
    const int m0 = blockIdx.x * 128;
    const int n0 = blockIdx.y * 64;

    const int xrow[4] = { (tid) >> 3, (tid + 256) >> 3, (tid + 512) >> 3, (tid + 768) >> 3 };
    const int xcol4 = (tid & 7) * 4;
    const int brow[2] = { tid >> 4, (tid + 256) >> 4 };
    const int bcol4 = (tid & 15) * 4;

    size_t pre[4];
    #pragma unroll
    for (int i = 0; i < 4; i++) {
        int m = m0 + xrow[i];
        int bb = m / NN, nn = m % NN;
        pre[i] = ((size_t)bb * NN + nn) * DHE;
    }

    float acc[2][4][4];
    #pragma unroll
    for (int am = 0; am < 2; am++)
        #pragma unroll
        for (int an = 0; an < 4; an++)
            #pragma unroll
            for (int e = 0; e < 4; e++) acc[am][an][e] = 0.f;

    auto load_panel = [&](int stage, int kt) {
        const int h = kt >> 1;
        const int dh0 = (kt & 1) * 32;
        const size_t hoff = (size_t)h * BB * NN * DHE;
        uint32_t xs = smem_base + (stage * X_TILE_U32) * 4;
        #pragma unroll
        for (int i = 0; i < 4; i++) {
            cp16(xs + (xrow[i] * XS_STRIDE + xcol4) * 4,
                 g_ao + hoff + pre[i] + dh0 + xcol4);
        }
        uint32_t bs = smem_base + (2 * X_TILE_U32 + stage * B_TILE_U32) * 4;
        #pragma unroll
        for (int i = 0; i < 2; i++) {
            cp16(bs + (brow[i] * BS_STRIDE + bcol4) * 4,
                 W + (size_t)(kt * 32 + brow[i]) * DD + n0 + bcol4);
        }
    };

    uint32_t (*Xsv)[XS_STRIDE] = (uint32_t(*)[XS_STRIDE])smbuf;
    uint32_t (*Bsv)[BS_STRIDE] = (uint32_t(*)[BS_STRIDE])(smbuf + 2 * X_TILE_U32);

    load_panel(0, 0);
    CP_COMMIT();

    const int NP = DD / 32;
    for (int kt = 0; kt < NP; kt++) {
        if (kt + 1 < NP) {
            load_panel((kt + 1) & 1, kt + 1);
            CP_COMMIT();
            CP_WAIT(1);
        } else {
            CP_WAIT(0);
        }
        __syncthreads();

        const int st = kt & 1;
        uint32_t (*Xs)[XS_STRIDE] = Xsv + st * 128;
        uint32_t (*Bs)[BS_STRIDE] = Bsv + st * 32;
        #pragma unroll
        for (int ks = 0; ks < 32; ks += 8) {
            uint32_t a[2][4];
            #pragma unroll
            for (int am = 0; am < 2; am++) {
                int row = wm * 32 + am * 16;
                a[am][0] = Xs[row + g][ks + t];
                a[am][1] = Xs[row + 8 + g][ks + t];
                a[am][2] = Xs[row + g][ks + t + 4];
                a[am][3] = Xs[row + 8 + g][ks + t + 4];
            }
            #pragma unroll
            for (int an = 0; an < 4; an++) {
                int n = wn * 32 + an * 8 + g;
                uint32_t b0 = Bs[ks + t][n];
                uint32_t b1 = Bs[ks + t + 4][n];
                mma_tf32(acc[0][an], a[0][0], a[0][1], a[0][2], a[0][3], b0, b1);
                mma_tf32(acc[1][an], a[1][0], a[1][1], a[1][2], a[1][3], b0, b1);
            }
        }
        __syncthreads();
    }

    #pragma unroll
    for (int an = 0; an < 4; an++) {
        int col = n0 + wn * 32 + an * 8 + 2 * t;
        #pragma unroll
        for (int cc = 0; cc < 2; cc++) {
            int e = col + cc;
            float bv_ = bias[e];
            #pragma unroll
            for (int am = 0; am < 2; am++)
                #pragma unroll
                for (int hl = 0; hl < 2; hl++) {
                    int m = m0 + wm * 32 + am * 16 + g + hl * 8;
                    g_o[(size_t)m * DD + e] =
                        acc[am][an][hl * 2 + cc] + bv_ + query[(size_t)m * DD + e];
                }
        }
    }
}

// ============================================================
// K6: LayerNorm over D=512 per row -> d_out
// ============================================================
__global__ __launch_bounds__(256) void ln_kernel(const float* __restrict__ gamma,
                                                 const float* __restrict__ beta,
                                                 float* __restrict__ out)
{
    const int m = blockIdx.x;
    const float* xr = g_o + (size_t)m * DD;
    const int tid = threadIdx.x;

    __shared__ float red[8];

    float x0 = xr[tid], x1 = xr[tid + 256];
    float s = x0 + x1;
    #pragma unroll
    for (int off = 16; off > 0; off >>= 1)
        s += __shfl_xor_sync(0xffffffff, s, off);
    if ((tid & 31) == 0) red[tid >> 5] = s;
    __syncthreads();
    float tot = 0.f;
    #pragma unroll
    for (int w = 0; w < 8; w++) tot += red[w];
    float mean = tot * (1.f / DD);

    float d0 = x0 - mean, d1 = x1 - mean;
    float ss = d0 * d0 + d1 * d1;
    #pragma unroll
    for (int off = 16; off > 0; off >>= 1)
        ss += __shfl_xor_sync(0xffffffff, ss, off);
    __syncthreads();
    if ((tid & 31) == 0) red[tid >> 5] = ss;
    __syncthreads();
    float tss = 0.f;
    #pragma unroll
    for (int w = 0; w < 8; w++) tss += red[w];
    float var = tss * (1.f / DD);
    float rstd = rsqrtf(var + 1e-7f);

    out[(size_t)m * DD + tid]       = gamma[tid]       * d0 * rstd + beta[tid];
    out[(size_t)m * DD + tid + 256] = gamma[tid + 256] * d1 * rstd + beta[tid + 256];
}

// ============================================================
extern "C" void kernel_launch(void* const* d_in, const int* in_sizes, int n_in,
                              void* d_out, int out_size)
{
    const float* query = (const float*)d_in[0];
    const float* Wq    = (const float*)d_in[1];
    const float* bq    = (const float*)d_in[2];
    const float* Wk    = (const float*)d_in[3];
    const float* bk    = (const float*)d_in[4];
    const float* Wv    = (const float*)d_in[5];
    const float* bv    = (const float*)d_in[6];
    const float* Wh    = (const float*)d_in[7];
    const float* bh    = (const float*)d_in[8];
    const float* pos_k = (const float*)d_in[9];
    const float* gamma = (const float*)d_in[10];
    const float* beta  = (const float*)d_in[11];
    const int*   vl    = (const int*)d_in[12];
    float* out = (float*)d_out;

    const int FLASH_SMEM = 6 * 64 * 68 * 4;                         // 104448 B
    const int QKV_SMEM   = (2 * X_TILE_U32 + 6 * B_TILE_U32) * 4;   // 89088 B
    const int OUT_SMEM   = (2 * X_TILE_U32 + 2 * B_TILE_U32) * 4;   // 54272 B

    static int smem_set = 0;
    if (!smem_set) {
        cudaFuncSetAttribute(flash_kernel,
                             cudaFuncAttributeMaxDynamicSharedMemorySize, FLASH_SMEM);
        cudaFuncSetAttribute(qkv_fused,
                             cudaFuncAttributeMaxDynamicSharedMemorySize, QKV_SMEM);
        cudaFuncSetAttribute(outproj_gemm,
                             cudaFuncAttributeMaxDynamicSharedMemorySize, OUT_SMEM);
        smem_set = 1;
    }

    qkv_fused<<<dim3(BN / 128, DD / 64), 256, QKV_SMEM>>>(query, Wq, bq, Wk, bk, Wv, bv);

    flash_kernel<<<dim3(9, HB), 128, FLASH_SMEM>>>(pos_k, vl);

    outproj_gemm<<<dim3(BN / 128, DD / 64), 256, OUT_SMEM>>>(Wh, bh, query);
    ln_kernel<<<BN, 256>>>(gamma, beta, out);
}

// round 11
// speedup vs baseline: 1.2141x; 1.0257x over previous
#include <cuda_runtime.h>
#include <cstdint>
#include <math.h>

#define BB 32
#define NN 540
#define DD 512
#define HH 8
#define DHE 64
#define HB (HH*BB)          // 256
#define BN (BB*NN)          // 17280
#define PCLIP 539
#define RLEN (2*PCLIP+1)    // 1079

// -------- scratch (device globals) --------
__device__ float g_q[(size_t)HB*NN*DHE];   // tf32 bits, q pre-scaled by 0.125
__device__ float g_k[(size_t)HB*NN*DHE];   // tf32 bits
__device__ float g_v[(size_t)HB*NN*DHE];   // tf32 bits
__device__ float g_ao[(size_t)HB*NN*DHE];  // attn@v, tf32 bits, head-major
__device__ float g_o[(size_t)BN*DD];       // pre-LN (fp32)

// -------- helpers --------
__device__ __forceinline__ uint32_t f2tf(float f) {
    uint32_t u;
    asm("cvt.rna.tf32.f32 %0, %1;" : "=r"(u) : "f"(f));
    return u;
}

__device__ __forceinline__ void mma_tf32(float c[4],
                                         uint32_t a0, uint32_t a1, uint32_t a2, uint32_t a3,
                                         uint32_t b0, uint32_t b1) {
    asm volatile(
        "mma.sync.aligned.m16n8k8.row.col.f32.tf32.tf32.f32 "
        "{%0,%1,%2,%3}, {%4,%5,%6,%7}, {%8,%9}, {%0,%1,%2,%3};\n"
        : "+f"(c[0]), "+f"(c[1]), "+f"(c[2]), "+f"(c[3])
        : "r"(a0), "r"(a1), "r"(a2), "r"(a3), "r"(b0), "r"(b1));
}

__device__ __forceinline__ void cp16(uint32_t smem_u32_addr, const void* gptr) {
    asm volatile("cp.async.cg.shared.global [%0], [%1], 16;\n"
                 :: "r"(smem_u32_addr), "l"(gptr));
}
#define CP_COMMIT() asm volatile("cp.async.commit_group;\n" ::)
#define CP_WAIT(n)  asm volatile("cp.async.wait_group %0;\n" :: "n"(n))

// smem tiling constants for pipelined GEMMs
#define XS_STRIDE 36
#define X_TILE_U32 (128*XS_STRIDE)     // 4608
#define BS_STRIDE 68
#define B_TILE_U32 (32*BS_STRIDE)      // 2176

// ============================================================
// K1: fused QKV projection, tf32 mma, cp.async 2-stage pipeline.
// ============================================================
__global__ __launch_bounds__(256) void qkv_fused(const float* __restrict__ X,
                                                 const float* __restrict__ Wq, const float* __restrict__ bq,
                                                 const float* __restrict__ Wk, const float* __restrict__ bk,
                                                 const float* __restrict__ Wv, const float* __restrict__ bv)
{
    extern __shared__ uint32_t smbuf[];
    const uint32_t smem_base = (uint32_t)__cvta_generic_to_shared(smbuf);

    const int tid = threadIdx.x;
    const int lane = tid & 31, warp = tid >> 5;
    const int g = lane >> 2, t = lane & 3;
    const int wm = warp >> 1, wn = warp & 1;
    const int m0 = blockIdx.x * 128;
    const int n0 = blockIdx.y * 64;

    const float* Ws[3] = {Wq, Wk, Wv};

    const int xrow[4] = { (tid) >> 3, (tid + 256) >> 3, (tid + 512) >> 3, (tid + 768) >> 3 };
    const int xcol4 = (tid & 7) * 4;
    const int brow[2] = { tid >> 4, (tid + 256) >> 4 };
    const int bcol4 = (tid & 15) * 4;

    float acc[3][2][4][4];
    #pragma unroll
    for (int w = 0; w < 3; w++)
        #pragma unroll
        for (int am = 0; am < 2; am++)
            #pragma unroll
            for (int an = 0; an < 4; an++)
                #pragma unroll
                for (int e = 0; e < 4; e++) acc[w][am][an][e] = 0.f;

    auto load_panel = [&](int stage, int k0) {
        uint32_t xs = smem_base + (stage * X_TILE_U32) * 4;
        #pragma unroll
        for (int i = 0; i < 4; i++) {
            cp16(xs + (xrow[i] * XS_STRIDE + xcol4) * 4,
                 X + (size_t)(m0 + xrow[i]) * DD + k0 + xcol4);
        }
        #pragma unroll
        for (int w = 0; w < 3; w++) {
            uint32_t bs = smem_base + (2 * X_TILE_U32 + (stage * 3 + w) * B_TILE_U32) * 4;
            #pragma unroll
            for (int i = 0; i < 2; i++) {
                cp16(bs + (brow[i] * BS_STRIDE + bcol4) * 4,
                     Ws[w] + (size_t)(k0 + brow[i]) * DD + n0 + bcol4);
            }
        }
    };

    uint32_t (*Xsv)[XS_STRIDE] = (uint32_t(*)[XS_STRIDE])smbuf;
    uint32_t (*Bsv)[BS_STRIDE] = (uint32_t(*)[BS_STRIDE])(smbuf + 2 * X_TILE_U32);

    load_panel(0, 0);
    CP_COMMIT();

    const int NP = DD / 32;
    for (int kt = 0; kt < NP; kt++) {
        if (kt + 1 < NP) {
            load_panel((kt + 1) & 1, (kt + 1) * 32);
            CP_COMMIT();
            CP_WAIT(1);
        } else {
            CP_WAIT(0);
        }
        __syncthreads();

        const int st = kt & 1;
        uint32_t (*Xs)[XS_STRIDE] = Xsv + st * 128;
        #pragma unroll
        for (int ks = 0; ks < 32; ks += 8) {
            uint32_t a[2][4];
            #pragma unroll
            for (int am = 0; am < 2; am++) {
                int row = wm * 32 + am * 16;
                a[am][0] = Xs[row + g][ks + t];
                a[am][1] = Xs[row + 8 + g][ks + t];
                a[am][2] = Xs[row + g][ks + t + 4];
                a[am][3] = Xs[row + 8 + g][ks + t + 4];
            }
            #pragma unroll
            for (int w = 0; w < 3; w++) {
                uint32_t (*Bs)[BS_STRIDE] = Bsv + (st * 3 + w) * 32;
                #pragma unroll
                for (int an = 0; an < 4; an++) {
                    int n = wn * 32 + an * 8 + g;
                    uint32_t b0 = Bs[ks + t][n];
                    uint32_t b1 = Bs[ks + t + 4][n];
                    mma_tf32(acc[w][0][an], a[0][0], a[0][1], a[0][2], a[0][3], b0, b1);
                    mma_tf32(acc[w][1][an], a[1][0], a[1][1], a[1][2], a[1][3], b0, b1);
                }
            }
        }
        __syncthreads();
    }

    int mb[2][2], mn[2][2];
    #pragma unroll
    for (int am = 0; am < 2; am++)
        #pragma unroll
        for (int hl = 0; hl < 2; hl++) {
            int m = m0 + wm * 32 + am * 16 + g + hl * 8;
            mb[am][hl] = m / NN;
            mn[am][hl] = m % NN;
        }

    const float* biases[3] = {bq, bk, bv};
    #pragma unroll
    for (int w = 0; w < 3; w++) {
        float* out = (w == 0) ? g_q : (w == 1) ? g_k : g_v;
        const float* bias = biases[w];
        float scl = (w == 0) ? 0.125f : 1.0f;
        #pragma unroll
        for (int an = 0; an < 4; an++) {
            int col = n0 + wn * 32 + an * 8 + 2 * t;
            #pragma unroll
            for (int cc = 0; cc < 2; cc++) {
                int e = col + cc;
                int h = e >> 6, dh = e & 63;
                float bv_ = bias[e];
                #pragma unroll
                for (int am = 0; am < 2; am++)
                    #pragma unroll
                    for (int hl = 0; hl < 2; hl++) {
                        float val = (acc[w][am][an][hl * 2 + cc] + bv_) * scl;
                        out[((size_t)(h * BB + mb[am][hl]) * NN + mn[am][hl]) * DHE + dh]
                            = __uint_as_float(f2tf(val));
                    }
            }
        }
    }
}

// ============================================================
// K3: flash attention, restructured dataflow:
//  - q fragments in registers (A-operand of S and R mma)
//  - K/P share ping-pong buffers C0/C1 (K dead after S-mma)
//  - R-mma moved after softmax (sacc reused); 2 syncthreads/iter
//  - cp.async groups: pos, v committed before k (mid-iter wait frees pos+v)
// 128 threads (4 warps x 16 rows). smem: 6 x 64x68 u32 = 104448 B.
// ============================================================
__global__ __launch_bounds__(128) void flash_kernel(const float* __restrict__ pos_k,
                                                    const int* __restrict__ vl)
{
    extern __shared__ uint32_t fsm[];
    uint32_t* c0v = fsm;                       // C0: q stage -> K/P ping
    uint32_t* c1v = fsm + 4352;                // C1: K/P pong
    uint32_t* vsv = fsm + 2 * 4352;            // V tile
    uint32_t* ppv = fsm + 3 * 4352;            // pos chunk
    float* Xf0 = (float*)(fsm + 4 * 4352);     // R ping (fp32)
    float* Xf1 = (float*)(fsm + 5 * 4352);     // R pong

    const uint32_t smem_base = (uint32_t)__cvta_generic_to_shared(fsm);
    const uint32_t c0_b = smem_base;
    const uint32_t c1_b = smem_base + 4352 * 4;
    const uint32_t vs_b = smem_base + 2 * 4352 * 4;
    const uint32_t pp_b = smem_base + 3 * 4352 * 4;

    const int x = blockIdx.y;
    const int b = x & (BB - 1);
    const int vlen = vl[b];
    const int i0 = blockIdx.x * 64;
    const int base0 = PCLIP - i0;

    const int tid = threadIdx.x;
    const int lane = tid & 31, warp = tid >> 5;
    const int g = lane >> 2, t = lane & 3;
    const int ib = warp * 16;

    const float* qb = g_q + (size_t)x * NN * DHE;
    const float* kb = g_k + (size_t)x * NN * DHE;
    const float* vb = g_v + (size_t)x * NN * DHE;

    // per-thread staging coords: 8 chunks of (row, col4)
    const int lrow[8] = { tid >> 4, (tid + 128) >> 4, (tid + 256) >> 4, (tid + 384) >> 4,
                          (tid + 512) >> 4, (tid + 640) >> 4, (tid + 768) >> 4, (tid + 896) >> 4 };
    const int lc4 = (tid & 15) * 4;

    const int irow0 = i0 + ib + g;
    const int irow1 = irow0 + 8;
    const bool iok0 = irow0 < NN, iok1 = irow1 < NN;
    const int ii0 = ib + g, ii1 = ib + g + 8;

    auto issue_pos = [&](int c) {
        #pragma unroll
        for (int it = 0; it < 8; it++) {
            int r = lrow[it];
            int rel = base0 + 64 * c - 63 + r;
            rel = min(max(rel, 0), RLEN - 1);
            cp16(pp_b + (r * 68 + lc4) * 4, pos_k + (size_t)rel * DHE + lc4);
        }
    };
    auto issue_k = [&](uint32_t dst_b, int j0) {
        #pragma unroll
        for (int it = 0; it < 8; it++) {
            int r = lrow[it];
            int row = min(j0 + r, NN - 1);
            cp16(dst_b + (r * 68 + lc4) * 4, kb + (size_t)row * DHE + lc4);
        }
    };
    auto issue_v = [&](int j0) {
        #pragma unroll
        for (int it = 0; it < 8; it++) {
            int r = lrow[it];
            int row = min(j0 + r, NN - 1);
            cp16(vs_b + (r * 68 + lc4) * 4, vb + (size_t)row * DHE + lc4);
        }
    };
    auto issue_q = [&]() {
        #pragma unroll
        for (int it = 0; it < 8; it++) {
            int r = lrow[it];
            int row = min(i0 + r, NN - 1);
            cp16(c0_b + (r * 68 + lc4) * 4, qb + (size_t)row * DHE + lc4);
        }
    };

    // ---- prologue: stage q, read fragments, compute R chunks 0, 1 ----
    issue_q();     CP_COMMIT();
    issue_pos(0);  CP_COMMIT();
    CP_WAIT(0);
    __syncthreads();          // q + pos0 visible

    uint32_t aq[8][4];        // q fragments (A operand, shared by S and R mma)
    #pragma unroll
    for (int s = 0; s < 8; s++) {
        aq[s][0] = c0v[(ib + g) * 68 + 8 * s + t];
        aq[s][1] = c0v[(ib + 8 + g) * 68 + 8 * s + t];
        aq[s][2] = c0v[(ib + g) * 68 + 8 * s + t + 4];
        aq[s][3] = c0v[(ib + 8 + g) * 68 + 8 * s + t + 4];
    }

    // R chunk mma (aq regs x pp) into racc
    auto r_mma = [&](float racc[8][4]) {
        #pragma unroll
        for (int fn = 0; fn < 8; fn++)
            #pragma unroll
            for (int e = 0; e < 4; e++) racc[fn][e] = 0.f;
        #pragma unroll
        for (int s = 0; s < 8; s++) {
            #pragma unroll
            for (int fn = 0; fn < 8; fn++) {
                int n = fn * 8 + g;
                mma_tf32(racc[fn], aq[s][0], aq[s][1], aq[s][2], aq[s][3],
                         ppv[n * 68 + 8 * s + t], ppv[n * 68 + 8 * s + t + 4]);
            }
        }
    };
    auto r_store = [&](float* Xf, const float racc[8][4]) {
        #pragma unroll
        for (int fn = 0; fn < 8; fn++) {
            int c0w = fn * 8 + 2 * t;
            Xf[ii0 * 68 + c0w]     = racc[fn][0]; Xf[ii0 * 68 + c0w + 1] = racc[fn][1];
            Xf[ii1 * 68 + c0w]     = racc[fn][2]; Xf[ii1 * 68 + c0w + 1] = racc[fn][3];
        }
    };

    float sacc[8][4];
    r_mma(sacc);
    r_store(Xf0, sacc);
    __syncthreads();          // all warps done reading pp + c0 (q)
    issue_pos(1); CP_COMMIT();
    issue_k(c0_b, 0); CP_COMMIT();
    CP_WAIT(1);               // pos1 done; k0 in flight
    __syncthreads();
    r_mma(sacc);
    r_store(Xf1, sacc);
    // pp readers drain at first in-loop sync A

    float m0 = -1e30f, m1 = -1e30f, l0 = 0.f, l1 = 0.f;
    float oacc[8][4];
    #pragma unroll
    for (int fn = 0; fn < 8; fn++)
        #pragma unroll
        for (int e = 0; e < 4; e++) oacc[fn][e] = 0.f;

    int p = 0;
    for (int jt = 0; 64 * jt < vlen; jt++) {
        const int j0 = 64 * jt;
        uint32_t* Ca = (jt & 1) ? c1v : c0v;   // holds K(jt), then P(jt)
        const uint32_t Cb_b = (jt & 1) ? c0_b : c1_b;

        CP_WAIT(0);           // K(jt) landed
        __syncthreads();      // sync A: K visible; vs/pp/Cb free (prev iter done)
        issue_pos(jt + 2); CP_COMMIT();   // G: pos
        issue_v(j0);       CP_COMMIT();   // G: v
        issue_k(Cb_b, j0 + 64); CP_COMMIT(); // G: k(jt+1) — full-iter lead

        // ---- S = q · k^T (A regs, B from Ca) ----
        #pragma unroll
        for (int fn = 0; fn < 8; fn++)
            #pragma unroll
            for (int e = 0; e < 4; e++) sacc[fn][e] = 0.f;
        #pragma unroll
        for (int s = 0; s < 8; s++) {
            #pragma unroll
            for (int fn = 0; fn < 8; fn++) {
                int n = fn * 8 + g;
                mma_tf32(sacc[fn], aq[s][0], aq[s][1], aq[s][2], aq[s][3],
                         Ca[n * 68 + 8 * s + t], Ca[n * 68 + 8 * s + t + 4]);
            }
        }

        // ---- gather bias from Xf chunks; mask; tile row max ----
        float* Af = p ? Xf1 : Xf0;
        float* Bf = p ? Xf0 : Xf1;
        float tm0 = -1e30f, tm1 = -1e30f;
        const bool full = (j0 + 64 <= vlen);
        if (full) {
            #pragma unroll
            for (int fn = 0; fn < 8; fn++) {
                int jj = fn * 8 + 2 * t;
                int d00 = jj - ii0;
                int d10 = jj - ii1;
                float r00 = (d00 > 0)     ? Bf[ii0 * 68 + d00 - 1] : Af[ii0 * 68 + d00 + 63];
                float r01 = (d00 + 1 > 0) ? Bf[ii0 * 68 + d00]     : Af[ii0 * 68 + d00 + 64];
                float r10 = (d10 > 0)     ? Bf[ii1 * 68 + d10 - 1] : Af[ii1 * 68 + d10 + 63];
                float r11 = (d10 + 1 > 0) ? Bf[ii1 * 68 + d10]     : Af[ii1 * 68 + d10 + 64];
                sacc[fn][0] += r00; sacc[fn][1] += r01;
                sacc[fn][2] += r10; sacc[fn][3] += r11;
                tm0 = fmaxf(tm0, fmaxf(sacc[fn][0], sacc[fn][1]));
                tm1 = fmaxf(tm1, fmaxf(sacc[fn][2], sacc[fn][3]));
            }
        } else {
            #pragma unroll
            for (int fn = 0; fn < 8; fn++) {
                int jj = fn * 8 + 2 * t;
                int j = j0 + jj;
                int d00 = jj - ii0;
                int d10 = jj - ii1;
                float r00 = (d00 > 0)     ? Bf[ii0 * 68 + d00 - 1] : Af[ii0 * 68 + d00 + 63];
                float r01 = (d00 + 1 > 0) ? Bf[ii0 * 68 + d00]     : Af[ii0 * 68 + d00 + 64];
                float r10 = (d10 > 0)     ? Bf[ii1 * 68 + d10 - 1] : Af[ii1 * 68 + d10 + 63];
                float r11 = (d10 + 1 > 0) ? Bf[ii1 * 68 + d10]     : Af[ii1 * 68 + d10 + 64];
                sacc[fn][0] = (j < vlen)     ? sacc[fn][0] + r00 : -1e30f;
                sacc[fn][1] = (j + 1 < vlen) ? sacc[fn][1] + r01 : -1e30f;
                sacc[fn][2] = (j < vlen)     ? sacc[fn][2] + r10 : -1e30f;
                sacc[fn][3] = (j + 1 < vlen) ? sacc[fn][3] + r11 : -1e30f;
                tm0 = fmaxf(tm0, fmaxf(sacc[fn][0], sacc[fn][1]));
                tm1 = fmaxf(tm1, fmaxf(sacc[fn][2], sacc[fn][3]));
            }
        }
        tm0 = fmaxf(tm0, __shfl_xor_sync(0xffffffffu, tm0, 1));
        tm0 = fmaxf(tm0, __shfl_xor_sync(0xffffffffu, tm0, 2));
        tm1 = fmaxf(tm1, __shfl_xor_sync(0xffffffffu, tm1, 1));
        tm1 = fmaxf(tm1, __shfl_xor_sync(0xffffffffu, tm1, 2));

        float mn0 = fmaxf(m0, tm0), mn1 = fmaxf(m1, tm1);
        float sc0 = __expf(m0 - mn0), sc1 = __expf(m1 - mn1);
        m0 = mn0; m1 = mn1;

        // ---- exp in place (sacc becomes P), row sums, rescale O ----
        float tl0 = 0.f, tl1 = 0.f;
        #pragma unroll
        for (int fn = 0; fn < 8; fn++) {
            sacc[fn][0] = __expf(sacc[fn][0] - mn0);
            sacc[fn][1] = __expf(sacc[fn][1] - mn0);
            sacc[fn][2] = __expf(sacc[fn][2] - mn1);
            sacc[fn][3] = __expf(sacc[fn][3] - mn1);
            tl0 += sacc[fn][0] + sacc[fn][1];
            tl1 += sacc[fn][2] + sacc[fn][3];
        }
        tl0 += __shfl_xor_sync(0xffffffffu, tl0, 1);
        tl0 += __shfl_xor_sync(0xffffffffu, tl0, 2);
        tl1 += __shfl_xor_sync(0xffffffffu, tl1, 1);
        tl1 += __shfl_xor_sync(0xffffffffu, tl1, 2);
        l0 = l0 * sc0 + tl0;
        l1 = l1 * sc1 + tl1;

        #pragma unroll
        for (int fn = 0; fn < 8; fn++) {
            oacc[fn][0] *= sc0; oacc[fn][1] *= sc0;
            oacc[fn][2] *= sc1; oacc[fn][3] *= sc1;
        }

        CP_WAIT(1);           // pos + v landed (k(jt+1) may fly)
        __syncthreads();      // sync B: all warps done S-reading Ca; pos/v visible

        // ---- P store into Ca (K slot now dead) ----
        #pragma unroll
        for (int fn = 0; fn < 8; fn++) {
            int c0w = fn * 8 + 2 * t;
            Ca[ii0 * 68 + c0w]     = f2tf(sacc[fn][0]);
            Ca[ii0 * 68 + c0w + 1] = f2tf(sacc[fn][1]);
            Ca[ii1 * 68 + c0w]     = f2tf(sacc[fn][2]);
            Ca[ii1 * 68 + c0w + 1] = f2tf(sacc[fn][3]);
        }

        // ---- Rnew = chunk(jt+2) (reads pp), retire old chunk ----
        r_mma(sacc);
        r_store(Af, sacc);
        p ^= 1;
        __syncwarp();         // own-warp P/R writes visible to warp

        // ---- O += P · V (A from Ca own rows, B from vs) ----
        #pragma unroll
        for (int s = 0; s < 8; s++) {
            uint32_t a0 = Ca[(ib + g) * 68 + 8 * s + t];
            uint32_t a1 = Ca[(ib + 8 + g) * 68 + 8 * s + t];
            uint32_t a2 = Ca[(ib + g) * 68 + 8 * s + t + 4];
            uint32_t a3 = Ca[(ib + 8 + g) * 68 + 8 * s + t + 4];
            #pragma unroll
            for (int fn = 0; fn < 8; fn++) {
                int n = fn * 8 + g;
                mma_tf32(oacc[fn], a0, a1, a2, a3,
                         vsv[(8 * s + t) * 68 + n], vsv[(8 * s + t + 4) * 68 + n]);
            }
        }
        __syncwarp();
    }
    CP_WAIT(0);               // drain trailing k

    float inv0 = 1.f / l0, inv1 = 1.f / l1;
    float* ob = g_ao + (size_t)x * NN * DHE;
    #pragma unroll
    for (int fn = 0; fn < 8; fn++) {
        int dh = fn * 8 + 2 * t;
        if (iok0) {
            float2 v;
            v.x = __uint_as_float(f2tf(oacc[fn][0] * inv0));
            v.y = __uint_as_float(f2tf(oacc[fn][1] * inv0));
            *(float2*)(ob + (size_t)irow0 * DHE + dh) = v;
        }
        if (iok1) {
            float2 v;
            v.x = __uint_as_float(f2tf(oacc[fn][2] * inv1));
            v.y = __uint_as_float(f2tf(oacc[fn][3] * inv1));
            *(float2*)(ob + (size_t)irow1 * DHE + dh) = v;
        }
    }
}

// ============================================================
// K5: output projection, cp.async 2-stage pipeline, block tile 128x64.
// ============================================================
__global__ __launch_bounds__(256) void outproj_gemm(const float* __restrict__ W,
                                                    const float* __restrict__ bias,
                                                    const float* __restrict__ query)
{
    extern __shared__ uint32_t smbuf[];
    const uint32_t smem_base = (uint32_t)__cvta_generic_to_shared(smbuf);

    const int tid = threadIdx.x;
    const int lane = tid & 31, warp = tid >> 5;
    const int g = lane >> 2, t = lane & 3;
    const int wm = warp >> 1, wn = warp & 1;
    const int m0 = blockIdx.x * 128;
    const int n0 = blockIdx.y * 64;

    const int xrow[4] = { (tid) >> 3, (tid + 256) >> 3, (tid + 512) >> 3, (tid + 768) >> 3 };
    const int xcol4 = (tid & 7) * 4;
    const int brow[2] = { tid >> 4, (tid + 256) >> 4 };
    const int bcol4 = (tid & 15) * 4;

    size_t pre[4];
    #pragma unroll
    for (int i = 0; i < 4; i++) {
        int m = m0 + xrow[i];
        int bb = m / NN, nn = m % NN;
        pre[i] = ((size_t)bb * NN + nn) * DHE;
    }

    float acc[2][4][4];
    #pragma unroll
    for (int am = 0; am < 2; am++)
        #pragma unroll
        for (int an = 0; an < 4; an++)
            #pragma unroll
            for (int e = 0; e < 4; e++) acc[am][an][e] = 0.f;

    auto load_panel = [&](int stage, int kt) {
        const int h = kt >> 1;
        const int dh0 = (kt & 1) * 32;
        const size_t hoff = (size_t)h * BB * NN * DHE;
        uint32_t xs = smem_base + (stage * X_TILE_U32) * 4;
        #pragma unroll
        for (int i = 0; i < 4; i++) {
            cp16(xs + (xrow[i] * XS_STRIDE + xcol4) * 4,
                 g_ao + hoff + pre[i] + dh0 + xcol4);
        }
        uint32_t bs = smem_base + (2 * X_TILE_U32 + stage * B_TILE_U32) * 4;
        #pragma unroll
        for (int i = 0; i < 2; i++) {
            cp16(bs + (brow[i] * BS_STRIDE + bcol4) * 4,
                 W + (size_t)(kt * 32 + brow[i]) * DD + n0 + bcol4);
        }
    };

    uint32_t (*Xsv)[XS_STRIDE] = (uint32_t(*)[XS_STRIDE])smbuf;
    uint32_t (*Bsv)[BS_STRIDE] = (uint32_t(*)[BS_STRIDE])(smbuf + 2 * X_TILE_U32);

    load_panel(0, 0);
    CP_COMMIT();

    const int NP = DD / 32;
    for (int kt = 0; kt < NP; kt++) {
        if (kt + 1 < NP) {
            load_panel((kt + 1) & 1, kt + 1);
            CP_COMMIT();
            CP_WAIT(1);
        } else {
            CP_WAIT(0);
        }
        __syncthreads();

        const int st = kt & 1;
        uint32_t (*Xs)[XS_STRIDE] = Xsv + st * 128;
        uint32_t (*Bs)[BS_STRIDE] = Bsv + st * 32;
        #pragma unroll
        for (int ks = 0; ks < 32; ks += 8) {
            uint32_t a[2][4];
            #pragma unroll
            for (int am = 0; am < 2; am++) {
                int row = wm * 32 + am * 16;
                a[am][0] = Xs[row + g][ks + t];
                a[am][1] = Xs[row + 8 + g][ks + t];
                a[am][2] = Xs[row + g][ks + t + 4];
                a[am][3] = Xs[row + 8 + g][ks + t + 4];
            }
            #pragma unroll
            for (int an = 0; an < 4; an++) {
                int n = wn * 32 + an * 8 + g;
                uint32_t b0 = Bs[ks + t][n];
                uint32_t b1 = Bs[ks + t + 4][n];
                mma_tf32(acc[0][an], a[0][0], a[0][1], a[0][2], a[0][3], b0, b1);
                mma_tf32(acc[1][an], a[1][0], a[1][1], a[1][2], a[1][3], b0, b1);
            }
        }
        __syncthreads();
    }

    #pragma unroll
    for (int an = 0; an < 4; an++) {
        int col = n0 + wn * 32 + an * 8 + 2 * t;
        #pragma unroll
        for (int cc = 0; cc < 2; cc++) {
            int e = col + cc;
            float bv_ = bias[e];
            #pragma unroll
            for (int am = 0; am < 2; am++)
                #pragma unroll
                for (int hl = 0; hl < 2; hl++) {
                    int m = m0 + wm * 32 + am * 16 + g + hl * 8;
                    g_o[(size_t)m * DD + e] =
                        acc[am][an][hl * 2 + cc] + bv_ + query[(size_t)m * DD + e];
                }
        }
    }
}

// ============================================================
// K6: LayerNorm over D=512 per row -> d_out
// ============================================================
__global__ __launch_bounds__(256) void ln_kernel(const float* __restrict__ gamma,
                                                 const float* __restrict__ beta,
                                                 float* __restrict__ out)
{
    const int m = blockIdx.x;
    const float* xr = g_o + (size_t)m * DD;
    const int tid = threadIdx.x;

    __shared__ float red[8];

    float x0 = xr[tid], x1 = xr[tid + 256];
    float s = x0 + x1;
    #pragma unroll
    for (int off = 16; off > 0; off >>= 1)
        s += __shfl_xor_sync(0xffffffff, s, off);
    if ((tid & 31) == 0) red[tid >> 5] = s;
    __syncthreads();
    float tot = 0.f;
    #pragma unroll
    for (int w = 0; w < 8; w++) tot += red[w];
    float mean = tot * (1.f / DD);

    float d0 = x0 - mean, d1 = x1 - mean;
    float ss = d0 * d0 + d1 * d1;
    #pragma unroll
    for (int off = 16; off > 0; off >>= 1)
        ss += __shfl_xor_sync(0xffffffff, ss, off);
    __syncthreads();
    if ((tid & 31) == 0) red[tid >> 5] = ss;
    __syncthreads();
    float tss = 0.f;
    #pragma unroll
    for (int w = 0; w < 8; w++) tss += red[w];
    float var = tss * (1.f / DD);
    float rstd = rsqrtf(var + 1e-7f);

    out[(size_t)m * DD + tid]       = gamma[tid]       * d0 * rstd + beta[tid];
    out[(size_t)m * DD + tid + 256] = gamma[tid + 256] * d1 * rstd + beta[tid + 256];
}

// ============================================================
extern "C" void kernel_launch(void* const* d_in, const int* in_sizes, int n_in,
                              void* d_out, int out_size)
{
    const float* query = (const float*)d_in[0];
    const float* Wq    = (const float*)d_in[1];
    const float* bq    = (const float*)d_in[2];
    const float* Wk    = (const float*)d_in[3];
    const float* bk    = (const float*)d_in[4];
    const float* Wv    = (const float*)d_in[5];
    const float* bv    = (const float*)d_in[6];
    const float* Wh    = (const float*)d_in[7];
    const float* bh    = (const float*)d_in[8];
    const float* pos_k = (const float*)d_in[9];
    const float* gamma = (const float*)d_in[10];
    const float* beta  = (const float*)d_in[11];
    const int*   vl    = (const int*)d_in[12];
    float* out = (float*)d_out;

    const int FLASH_SMEM = 6 * 64 * 68 * 4;                         // 104448 B
    const int QKV_SMEM   = (2 * X_TILE_U32 + 6 * B_TILE_U32) * 4;   // 89088 B
    const int OUT_SMEM   = (2 * X_TILE_U32 + 2 * B_TILE_U32) * 4;   // 54272 B

    static int smem_set = 0;
    if (!smem_set) {
        cudaFuncSetAttribute(flash_kernel,
                             cudaFuncAttributeMaxDynamicSharedMemorySize, FLASH_SMEM);
        cudaFuncSetAttribute(qkv_fused,
                             cudaFuncAttributeMaxDynamicSharedMemorySize, QKV_SMEM);
        cudaFuncSetAttribute(outproj_gemm,
                             cudaFuncAttributeMaxDynamicSharedMemorySize, OUT_SMEM);
        smem_set = 1;
    }

    qkv_fused<<<dim3(BN / 128, DD / 64), 256, QKV_SMEM>>>(query, Wq, bq, Wk, bk, Wv, bv);

    flash_kernel<<<dim3(9, HB), 128, FLASH_SMEM>>>(pos_k, vl);

    outproj_gemm<<<dim3(BN / 128, DD / 64), 256, OUT_SMEM>>>(Wh, bh, query);
    ln_kernel<<<BN, 256>>>(gamma, beta, out);
}